// round 2
// baseline (speedup 1.0000x reference)
#include <cuda_runtime.h>

typedef unsigned long long u64;

#define NBATCH 512
#define NTT    257
#define NIVL   256
#define NIN    32
#define NH     128
#define NBN    256
#define NOUT   64
#define GRID_CTAS 128
#define TPB    256

// ---- shared memory layout (float offsets) ----
#define OFF_W3  0        // [256][128] k-major
#define OFF_W1  32768    // [128][8]   k-major
#define OFF_W2  33792    // [256][8]   k-major
#define OFF_B3  35840    // [128]
#define OFF_B1  35968    // [8]
#define OFF_B2  35976    // [8]
#define OFF_MW  35984    // [128][2]
#define OFF_SW  36240    // [128][2]
#define OFF_MB  36496    // [2]
#define OFF_SB  36498    // [2]
#define OFF_DX  36500    // [128][32]
#define OFF_ACT 40596    // 2 x [16][128] double-buffered act chunks
#define OFF_KP  44692    // [128][17] stage-3 partials
#define SMEM_FLOATS 46868
#define SMEM_BYTES  (SMEM_FLOATS * 4)

// ---- global scratch (device globals: allowed; no cudaMalloc) ----
__device__ float g_zc[NBATCH * NH];
__device__ float g_h1[NBATCH * NBN];
__device__ float g_h2[NBATCH * NBN];

struct PadU { unsigned v; unsigned pad[31]; };
__device__ PadU g_cnt[4];   // zero-initialized at module load
__device__ PadU g_rel[4];

// ---- f32x2 helpers ----
__device__ __forceinline__ u64 pack2(float x, float y) {
    u64 r;
    asm("mov.b64 %0, {%1, %2};" : "=l"(r) : "f"(x), "f"(y));
    return r;
}
__device__ __forceinline__ float2 unpack2(u64 v) {
    float2 r;
    asm("mov.b64 {%0, %1}, %2;" : "=f"(r.x), "=f"(r.y) : "l"(v));
    return r;
}
__device__ __forceinline__ void fma2(u64& d, u64 a, u64 b) {
    asm("fma.rn.f32x2 %0, %1, %2, %0;" : "+l"(d) : "l"(a), "l"(b));
}

// tanh(x) = 1 - 2/(exp(2x)+1); ex2/rcp approx => ~1e-6 abs error, 2 MUFU ops
__device__ __forceinline__ float fast_tanh(float x) {
    float e;
    asm("ex2.approx.f32 %0, %1;" : "=f"(e) : "f"(x * 2.8853900817779268f));
    float r;
    asm("rcp.approx.f32 %0, %1;" : "=f"(r) : "f"(e + 1.0f));
    return fmaf(-2.0f, r, 1.0f);
}

// softplus matching jax: max(x,0) + log1p(exp(-|x|))
__device__ __forceinline__ float softplus_f(float x) {
    return fmaxf(x, 0.0f) + log1pf(expf(-fabsf(x)));
}

// ---- 32-CTA group barrier (monotonic phase, sense via counter value) ----
__device__ __forceinline__ void gbar(int grp, unsigned ph) {
    __syncthreads();
    if (threadIdx.x == 0) {
        __threadfence();
        unsigned old = atomicAdd(&g_cnt[grp].v, 1u);
        if (old == 31u) {
            g_cnt[grp].v = 0u;
            asm volatile("st.release.gpu.u32 [%0], %1;"
                         :: "l"(&g_rel[grp].v), "r"(ph) : "memory");
        } else {
            unsigned v;
            do {
                asm volatile("ld.acquire.gpu.u32 %0, [%1];"
                             : "=r"(v) : "l"(&g_rel[grp].v) : "memory");
            } while (v != ph);
        }
    }
    __syncthreads();
}

// final barrier resets g_rel to 0 so graph replays start from a clean state
__device__ __forceinline__ void gbar_reset(int grp) {
    __syncthreads();
    if (threadIdx.x == 0) {
        __threadfence();
        unsigned old = atomicAdd(&g_cnt[grp].v, 1u);
        if (old == 31u) {
            g_cnt[grp].v = 0u;
            asm volatile("st.release.gpu.u32 [%0], %1;"
                         :: "l"(&g_rel[grp].v), "r"(0u) : "memory");
        } else {
            unsigned v;
            do {
                asm volatile("ld.acquire.gpu.u32 %0, [%1];"
                             : "=r"(v) : "l"(&g_rel[grp].v) : "memory");
            } while (v != 0u);
        }
    }
}

// transpose-store a 16-k x 1-row strip of an activation chunk into smem (k-major)
__device__ __forceinline__ void stash(float* buf, int row, int kq2, float4 p0, float4 p1) {
    buf[(kq2 * 4 + 0) * 128 + row] = p0.x;
    buf[(kq2 * 4 + 1) * 128 + row] = p0.y;
    buf[(kq2 * 4 + 2) * 128 + row] = p0.z;
    buf[(kq2 * 4 + 3) * 128 + row] = p0.w;
    buf[(kq2 * 4 + 4) * 128 + row] = p1.x;
    buf[(kq2 * 4 + 5) * 128 + row] = p1.y;
    buf[(kq2 * 4 + 6) * 128 + row] = p1.z;
    buf[(kq2 * 4 + 7) * 128 + row] = p1.w;
}

// ---- MLP stage: out[128 rows, 8 cols] = relu(in[128,KT] @ Wslice + bslice) ----
template <int KT>
__device__ __forceinline__ void mlp_stage(const float* __restrict__ gin,
                                          const float* __restrict__ sW,
                                          const float* __restrict__ sb,
                                          float* __restrict__ goutBase,
                                          float* __restrict__ sAct, int tid) {
    const int r  = tid & 127;
    const int ch = tid >> 7;           // 0/1 -> cols ch*4..+4
    u64 acc0 = pack2(sb[ch * 4 + 0], sb[ch * 4 + 1]);
    u64 acc1 = pack2(sb[ch * 4 + 2], sb[ch * 4 + 3]);

    const int row = tid >> 1, kq2 = (tid & 1) << 1;
    const float* gsrc = gin + (size_t)row * KT;
    float4 p0 = __ldcg((const float4*)gsrc + kq2);
    float4 p1 = __ldcg((const float4*)gsrc + kq2 + 1);

    const int NCH = KT / 16;
#pragma unroll 1
    for (int kc = 0; kc < NCH; kc++) {
        float* buf = sAct + (kc & 1) * 2048;
        stash(buf, row, kq2, p0, p1);
        __syncthreads();
        if (kc + 1 < NCH) {
            const float* gn = gsrc + (kc + 1) * 16;
            p0 = __ldcg((const float4*)gn + kq2);
            p1 = __ldcg((const float4*)gn + kq2 + 1);
        }
#pragma unroll
        for (int k = 0; k < 16; k++) {
            float a  = buf[k * 128 + r];
            u64  aa  = pack2(a, a);
            const float* wr = sW + (kc * 16 + k) * 8 + ch * 4;
            u64 w0 = *(const u64*)wr;
            u64 w1 = *(const u64*)(wr + 2);
            fma2(acc0, aa, w0);
            fma2(acc1, aa, w1);
        }
    }
    float2 u0 = unpack2(acc0), u1 = unpack2(acc1);
    float4 o;
    o.x = fmaxf(u0.x, 0.f); o.y = fmaxf(u0.y, 0.f);
    o.z = fmaxf(u1.x, 0.f); o.w = fmaxf(u1.y, 0.f);
    __stcg((float4*)(goutBase + (size_t)r * NBN + ch * 4), o);
}

// ---- stage 3: k[128 rows, 4 h] = einsum(tanh(h2@W3slice + b3slice), dxdt) ----
__device__ __forceinline__ void stage3(const float* __restrict__ gin,
                                       const float* __restrict__ sW3,
                                       const float* __restrict__ sb3,
                                       const float* __restrict__ sDx,
                                       float* __restrict__ sAct,
                                       float* __restrict__ sKp,
                                       int tid, float& k0, float& k1) {
    const int ty = tid >> 4, tx = tid & 15;
    u64 acc[8][4];
#pragma unroll
    for (int j = 0; j < 8; j++)
#pragma unroll
        for (int p = 0; p < 4; p++) acc[j][p] = 0ull;

    const int row = tid >> 1, kq2 = (tid & 1) << 1;
    const float* gsrc = gin + (size_t)row * NBN;
    float4 p0 = __ldcg((const float4*)gsrc + kq2);
    float4 p1 = __ldcg((const float4*)gsrc + kq2 + 1);

#pragma unroll 1
    for (int kc = 0; kc < 16; kc++) {
        float* buf = sAct + (kc & 1) * 2048;
        stash(buf, row, kq2, p0, p1);
        __syncthreads();
        if (kc < 15) {
            const float* gn = gsrc + (kc + 1) * 16;
            p0 = __ldcg((const float4*)gn + kq2);
            p1 = __ldcg((const float4*)gn + kq2 + 1);
        }
#pragma unroll
        for (int k = 0; k < 16; k++) {
            const float* ar = buf + k * 128 + (ty << 3);
            float4 a0 = *(const float4*)ar;
            float4 a1 = *(const float4*)(ar + 4);
            const float* wr = sW3 + ((kc << 4) + k) * 128 + (tx << 3);
            u64 w00 = *(const u64*)(wr + 0);
            u64 w01 = *(const u64*)(wr + 2);
            u64 w10 = *(const u64*)(wr + 4);
            u64 w11 = *(const u64*)(wr + 6);
            float av[8] = {a0.x, a0.y, a0.z, a0.w, a1.x, a1.y, a1.z, a1.w};
#pragma unroll
            for (int j = 0; j < 8; j++) {
                u64 aa = pack2(av[j], av[j]);
                fma2(acc[j][0], aa, w00);
                fma2(acc[j][1], aa, w01);
                fma2(acc[j][2], aa, w10);
                fma2(acc[j][3], aa, w11);
            }
        }
    }

    // epilogue: bias + tanh + contract with dxdt over this thread's 8 i's
    const int hloc = tx >> 2;
    const int qq   = tx & 3;
    const int i0   = qq * 8;
    float part[8];
#pragma unroll
    for (int j = 0; j < 8; j++) {
        float s = 0.f;
        const float* dx = sDx + (ty * 8 + j) * 32 + i0;
#pragma unroll
        for (int p = 0; p < 4; p++) {
            float2 u = unpack2(acc[j][p]);
            int c = (tx << 3) + p * 2;
            float y0 = fast_tanh(u.x + sb3[c]);
            float y1 = fast_tanh(u.y + sb3[c + 1]);
            s = fmaf(y0, dx[p * 2], s);
            s = fmaf(y1, dx[p * 2 + 1], s);
        }
        part[j] = s;
    }
#pragma unroll
    for (int j = 0; j < 8; j++)
        sKp[(ty * 8 + j) * 17 + hloc * 4 + qq] = part[j];
    __syncthreads();

    // 4-way reduce into the z-owner layout: r = tid&127, hh = tid>>7
    const int r  = tid & 127;
    const int hh = tid >> 7;
    const float* kp = sKp + r * 17;
    const int c0 = (hh * 2) * 4;
    const int c1 = (hh * 2 + 1) * 4;
    k0 = (kp[c0] + kp[c0 + 1]) + (kp[c0 + 2] + kp[c0 + 3]);
    k1 = (kp[c1] + kp[c1 + 1]) + (kp[c1 + 2] + kp[c1 + 3]);
}

// ================= persistent kernel =================
__global__ void __launch_bounds__(TPB, 1)
cde_persistent(const float* __restrict__ t, const float* __restrict__ z0,
               const float* __restrict__ X,
               const float* __restrict__ W1, const float* __restrict__ b1,
               const float* __restrict__ W2, const float* __restrict__ b2,
               const float* __restrict__ W3, const float* __restrict__ b3,
               const float* __restrict__ mW, const float* __restrict__ mb,
               const float* __restrict__ sWp, const float* __restrict__ sbp,
               float* __restrict__ out) {
    extern __shared__ float sm[];
    float* sW3  = sm + OFF_W3;
    float* sW1  = sm + OFF_W1;
    float* sW2  = sm + OFF_W2;
    float* sb3  = sm + OFF_B3;
    float* sb1  = sm + OFF_B1;
    float* sb2  = sm + OFF_B2;
    float* smW  = sm + OFF_MW;
    float* ssW  = sm + OFF_SW;
    float* smb  = sm + OFF_MB;
    float* ssb  = sm + OFF_SB;
    float* sDx  = sm + OFF_DX;
    float* sAct = sm + OFF_ACT;
    float* sKp  = sm + OFF_KP;

    const int tid = threadIdx.x;
    const int bb  = blockIdx.x >> 5;   // batch-block group 0..3
    const int g   = blockIdx.x & 31;   // group-local id 0..31
    const int rowBase = bb * 128;

    // ---- stage weights into smem ----
    for (int i = tid; i < 256 * 32; i += TPB) {            // W3 slice [256][128]
        int k = i >> 5, c4 = i & 31;
        float4 v = __ldg((const float4*)(W3 + (size_t)k * 4096 + g * 128) + c4);
        *(float4*)(sW3 + k * 128 + c4 * 4) = v;
    }
    for (int i = tid; i < 128 * 2; i += TPB) {             // W1 slice [128][8]
        int k = i >> 1, c4 = i & 1;
        *(float4*)(sW1 + k * 8 + c4 * 4) =
            __ldg((const float4*)(W1 + (size_t)k * 256 + g * 8) + c4);
    }
    for (int i = tid; i < 256 * 2; i += TPB) {             // W2 slice [256][8]
        int k = i >> 1, c4 = i & 1;
        *(float4*)(sW2 + k * 8 + c4 * 4) =
            __ldg((const float4*)(W2 + (size_t)k * 256 + g * 8) + c4);
    }
    for (int i = tid; i < 128; i += TPB) sb3[i] = __ldg(&b3[g * 128 + i]);
    if (tid < 8)  sb1[tid] = __ldg(&b1[g * 8 + tid]);
    if (tid >= 8 && tid < 16) sb2[tid - 8] = __ldg(&b2[g * 8 + tid - 8]);
    for (int i = tid; i < 256; i += TPB) {                 // mW/sW slices [128][2]
        int h = i >> 1, c = i & 1;
        smW[i] = __ldg(&mW[(size_t)h * 64 + g * 2 + c]);
        ssW[i] = __ldg(&sWp[(size_t)h * 64 + g * 2 + c]);
    }
    if (tid < 2)  smb[tid] = __ldg(&mb[g * 2 + tid]);
    if (tid >= 2 && tid < 4) ssb[tid - 2] = __ldg(&sbp[g * 2 + tid - 2]);
    __syncthreads();

    // ---- init owned z state ----
    const int r  = tid & 127;
    const int hh = tid >> 7;               // 0/1
    const int h0 = g * 4 + hh * 2;
    const int b  = rowBase + r;
    float zb0 = __ldg(&z0[(size_t)b * 128 + h0]);
    float zb1 = __ldg(&z0[(size_t)b * 128 + h0 + 1]);
    __stcg((float2*)(g_zc + (size_t)b * 128 + h0), make_float2(zb0, zb1));

    unsigned phase = 0;
    gbar(bb, ++phase);

#pragma unroll 1
    for (int tau = 0; tau < NIVL; tau++) {
        // dxdt for this CTA's 128 rows
        float t0v = __ldg(&t[tau]);
        float t1v = __ldg(&t[tau + 1]);
        float dti = t1v - t0v;
        float hstep = dti * 0.25f;
        __syncthreads();   // prior sDx consumers done (covered by barriers; belt&braces)
        for (int i = tid; i < 1024; i += TPB) {
            int rr = i >> 3, q = i & 7;
            const float* Xr = X + ((size_t)(rowBase + rr) * NTT + tau) * NIN;
            float4 x0 = __ldg((const float4*)Xr + q);
            float4 x1 = __ldg((const float4*)(Xr + NIN) + q);
            float4 d;
            d.x = (x1.x - x0.x) / dti;
            d.y = (x1.y - x0.y) / dti;
            d.z = (x1.z - x0.z) / dti;
            d.w = (x1.w - x0.w) / dti;
            *(float4*)(sDx + rr * 32 + (q << 2)) = d;
        }
        __syncthreads();

#pragma unroll 1
        for (int sub = 0; sub < 4; sub++) {
            float a0 = 0.f, a1 = 0.f, kp0 = 0.f, kp1 = 0.f;
#pragma unroll 1
            for (int s = 0; s < 4; s++) {
                float cs = (s == 0) ? 0.f : ((s == 3) ? 1.f : 0.5f);
                float zc0 = fmaf(cs * hstep, kp0, zb0);
                float zc1 = fmaf(cs * hstep, kp1, zb1);
                __stcg((float2*)(g_zc + (size_t)b * 128 + h0), make_float2(zc0, zc1));
                gbar(bb, ++phase);

                mlp_stage<128>(g_zc + (size_t)rowBase * 128, sW1, sb1,
                               g_h1 + (size_t)rowBase * 256 + g * 8, sAct, tid);
                gbar(bb, ++phase);

                mlp_stage<256>(g_h1 + (size_t)rowBase * 256, sW2, sb2,
                               g_h2 + (size_t)rowBase * 256 + g * 8, sAct, tid);
                gbar(bb, ++phase);

                float k0, k1;
                stage3(g_h2 + (size_t)rowBase * 256, sW3, sb3, sDx, sAct, sKp,
                       tid, k0, k1);
                float ws = (s == 0 || s == 3) ? 1.f : 2.f;
                a0 = fmaf(ws, k0, a0);
                a1 = fmaf(ws, k1, a1);
                kp0 = k0; kp1 = k1;
            }
            float h6 = hstep / 6.0f;
            zb0 = fmaf(h6, a0, zb0);
            zb1 = fmaf(h6, a1, zb1);
        }

        // ---- interval end: publish z, then output heads ----
        __stcg((float2*)(g_zc + (size_t)b * 128 + h0), make_float2(zb0, zb1));
        gbar(bb, ++phase);
        {
            const float* wsel = hh ? ssW : smW;
            float acc0 = hh ? ssb[0] : smb[0];
            float acc1 = hh ? ssb[1] : smb[1];
            const float* zrow = g_zc + (size_t)b * 128;
#pragma unroll 4
            for (int h = 0; h < 128; h++) {
                float zv = __ldcg(zrow + h);
                acc0 = fmaf(zv, wsel[h * 2 + 0], acc0);
                acc1 = fmaf(zv, wsel[h * 2 + 1], acc1);
            }
            if (hh) { acc0 = softplus_f(acc0); acc1 = softplus_f(acc1); }
            float* dst = out + (hh ? (size_t)NBATCH * NIVL * NOUT : 0)
                         + ((size_t)b * NIVL + tau) * NOUT + g * 2;
            dst[0] = acc0;
            dst[1] = acc1;
        }
    }

    gbar_reset(bb);   // leave barrier state zeroed for deterministic graph replay
}

extern "C" void kernel_launch(void* const* d_in, const int* in_sizes, int n_in,
                              void* d_out, int out_size) {
    const float* t   = (const float*)d_in[0];
    const float* z0  = (const float*)d_in[1];
    const float* X   = (const float*)d_in[2];
    const float* W1  = (const float*)d_in[3];
    const float* b1  = (const float*)d_in[4];
    const float* W2  = (const float*)d_in[5];
    const float* b2  = (const float*)d_in[6];
    const float* W3  = (const float*)d_in[7];
    const float* b3  = (const float*)d_in[8];
    const float* mW  = (const float*)d_in[9];
    const float* mb  = (const float*)d_in[10];
    const float* sW  = (const float*)d_in[11];
    const float* sb  = (const float*)d_in[12];
    float* out = (float*)d_out;

    cudaFuncSetAttribute(cde_persistent,
                         cudaFuncAttributeMaxDynamicSharedMemorySize, SMEM_BYTES);
    cde_persistent<<<GRID_CTAS, TPB, SMEM_BYTES>>>(t, z0, X, W1, b1, W2, b2,
                                                   W3, b3, mW, mb, sW, sb, out);
}